// round 1
// baseline (speedup 1.0000x reference)
#include <cuda_runtime.h>
#include <math.h>

// ---------------------------------------------------------------------------
// Scratch (device globals — no dynamic allocation allowed)
// ---------------------------------------------------------------------------
#define MAX_DST 262144                       // >= NE = 200000
__device__ float g_agg[(size_t)MAX_DST * 128];   // segment-sum accumulator
__device__ float g_cnt[MAX_DST];                 // segment counts (float)
__device__ float g_B[256 * 128];                 // [wl^T ; wr^T] for current type

// ---------------------------------------------------------------------------
// Build B[k][n]: k<128 -> wl[n][k], k>=128 -> wr[n][k-128]  (coalesced writes)
// ---------------------------------------------------------------------------
__global__ void prep_B_kernel(const float* __restrict__ wl,
                              const float* __restrict__ wr,
                              float* __restrict__ B) {
    int i = blockIdx.x * blockDim.x + threadIdx.x;   // 0 .. 32767
    int k = i >> 7;
    int n = i & 127;
    B[i] = (k < 128) ? wl[n * 128 + k] : wr[n * 128 + (k - 128)];
}

// ---------------------------------------------------------------------------
// Edge scatter: one warp per edge, float4 per lane.
// Gather x_src row (512B, perfectly coalesced per warp) and atomic-add into
// agg[dst]. Lane 0 bumps the count.
// ---------------------------------------------------------------------------
__global__ void scatter_kernel(const float* __restrict__ x_src,
                               const int* __restrict__ si,
                               const int* __restrict__ di,
                               int E,
                               float* __restrict__ agg,
                               float* __restrict__ cnt) {
    long long t = (long long)blockIdx.x * blockDim.x + threadIdx.x;
    int e = (int)(t >> 5);
    int c = (int)(t & 31);
    if (e >= E) return;
    int s = si[e];
    int d = di[e];
    float4 v = ((const float4*)(x_src + (size_t)s * 128))[c];
    float* dst = agg + (size_t)d * 128 + c * 4;
    atomicAdd(dst + 0, v.x);
    atomicAdd(dst + 1, v.y);
    atomicAdd(dst + 2, v.z);
    atomicAdd(dst + 3, v.w);
    if (c == 0) atomicAdd(cnt + d, 1.0f);
}

// ---------------------------------------------------------------------------
// Fused SAGE kernel: C = [x_dst | agg/max(cnt,1)] (M x 256) @ B (256 x 128)
// then + bias, L2-normalize each row, and write (or accumulate) into out.
// Block: 256 threads, computes 128 rows x 128 cols. Classic SGEMM tiling,
// BK=16, 8x8 register tile per thread (rows ty*4+i / 64+ty*4+i,
// cols tx*4+j / 64+tx*4+j). Row-norm reduction via shfl over the 16 tx lanes.
// ---------------------------------------------------------------------------
template <bool ACC>
__global__ void sage_gemm_kernel(const float* __restrict__ x_dst,
                                 const float* __restrict__ agg,
                                 const float* __restrict__ cnt,
                                 const float* __restrict__ B,
                                 const float* __restrict__ bias,
                                 float* __restrict__ out,
                                 int n_dst) {
    __shared__ float As[16][128];
    __shared__ float Bs[16][128];
    __shared__ float invc[128];

    int tid = threadIdx.x;          // 0..255
    int ty = tid >> 4;              // 0..15
    int tx = tid & 15;              // 0..15
    int rowBase = blockIdx.x * 128;

    if (tid < 128) {
        int gr = rowBase + tid;
        float c = (gr < n_dst) ? cnt[gr] : 1.0f;
        invc[tid] = 1.0f / fmaxf(c, 1.0f);
    }

    float acc[8][8];
#pragma unroll
    for (int i = 0; i < 8; i++)
#pragma unroll
        for (int j = 0; j < 8; j++) acc[i][j] = 0.f;

    for (int kt = 0; kt < 16; kt++) {
        int kBase = kt * 16;
        const float* srcA = (kt < 8) ? x_dst : agg;
        int kOff = (kt < 8) ? kBase : (kBase - 128);
        bool isAgg = (kt >= 8);

        __syncthreads();
        // Load A tile (128 rows x 16 cols) transposed into As[k][row]
#pragma unroll
        for (int it = 0; it < 2; it++) {
            int f = tid * 2 + it;          // 0..511 float4 items
            int r = f >> 2;                // row within tile
            int c4 = (f & 3) * 4;          // col within 16-wide k tile
            int gr = rowBase + r;
            float4 v = make_float4(0.f, 0.f, 0.f, 0.f);
            if (gr < n_dst)
                v = *(const float4*)(srcA + (size_t)gr * 128 + kOff + c4);
            if (isAgg) {
                float s = invc[r];
                v.x *= s; v.y *= s; v.z *= s; v.w *= s;
            }
            As[c4 + 0][r] = v.x;
            As[c4 + 1][r] = v.y;
            As[c4 + 2][r] = v.z;
            As[c4 + 3][r] = v.w;
        }
        // Load B tile (16 x 128) straight
#pragma unroll
        for (int it = 0; it < 2; it++) {
            int f = tid * 2 + it;          // 0..511
            int kr = f >> 5;               // 0..15
            int c4 = (f & 31) * 4;         // 0..124
            float4 v = *(const float4*)(B + (size_t)(kBase + kr) * 128 + c4);
            *(float4*)&Bs[kr][c4] = v;
        }
        __syncthreads();

#pragma unroll
        for (int k = 0; k < 16; k++) {
            float4 a0 = *(const float4*)&As[k][ty * 4];
            float4 a1 = *(const float4*)&As[k][64 + ty * 4];
            float4 b0 = *(const float4*)&Bs[k][tx * 4];
            float4 b1 = *(const float4*)&Bs[k][64 + tx * 4];
            float av[8] = {a0.x, a0.y, a0.z, a0.w, a1.x, a1.y, a1.z, a1.w};
            float bv[8] = {b0.x, b0.y, b0.z, b0.w, b1.x, b1.y, b1.z, b1.w};
#pragma unroll
            for (int i = 0; i < 8; i++)
#pragma unroll
                for (int j = 0; j < 8; j++) acc[i][j] += av[i] * bv[j];
        }
    }

    // Epilogue: bias, row L2-norm (reduce over 16 tx lanes), scale, write.
    float bvv[8];
    {
        float4 bb0 = *(const float4*)(bias + tx * 4);
        float4 bb1 = *(const float4*)(bias + 64 + tx * 4);
        bvv[0] = bb0.x; bvv[1] = bb0.y; bvv[2] = bb0.z; bvv[3] = bb0.w;
        bvv[4] = bb1.x; bvv[5] = bb1.y; bvv[6] = bb1.z; bvv[7] = bb1.w;
    }
#pragma unroll
    for (int i = 0; i < 8; i++) {
        float ss = 0.f;
#pragma unroll
        for (int j = 0; j < 8; j++) {
            acc[i][j] += bvv[j];
            ss += acc[i][j] * acc[i][j];
        }
        // lanes ty*16+tx: xor over {1,2,4,8} reduces across the 16 tx lanes
        ss += __shfl_xor_sync(0xffffffffu, ss, 1);
        ss += __shfl_xor_sync(0xffffffffu, ss, 2);
        ss += __shfl_xor_sync(0xffffffffu, ss, 4);
        ss += __shfl_xor_sync(0xffffffffu, ss, 8);
        float inv = 1.f / fmaxf(sqrtf(ss), 1e-12f);

        int r = (i < 4) ? (ty * 4 + i) : (64 + ty * 4 + (i - 4));
        int gr = rowBase + r;
        if (gr < n_dst) {
            float* p = out + (size_t)gr * 128;
            float4 o0 = make_float4(acc[i][0] * inv, acc[i][1] * inv,
                                    acc[i][2] * inv, acc[i][3] * inv);
            float4 o1 = make_float4(acc[i][4] * inv, acc[i][5] * inv,
                                    acc[i][6] * inv, acc[i][7] * inv);
            if (ACC) {
                float4 t0 = *(const float4*)(p + tx * 4);
                float4 t1 = *(const float4*)(p + 64 + tx * 4);
                o0.x += t0.x; o0.y += t0.y; o0.z += t0.z; o0.w += t0.w;
                o1.x += t1.x; o1.y += t1.y; o1.z += t1.z; o1.w += t1.w;
            }
            *(float4*)(p + tx * 4) = o0;
            *(float4*)(p + 64 + tx * 4) = o1;
        }
    }
}

// ---------------------------------------------------------------------------
// Host orchestration (graph-capturable: kernels + async memsets on stream 0)
// ---------------------------------------------------------------------------
extern "C" void kernel_launch(void* const* d_in, const int* in_sizes, int n_in,
                              void* d_out, int out_size) {
    const float* xa = (const float*)d_in[0];
    const float* xe = (const float*)d_in[1];
    const float* xf = (const float*)d_in[2];
    int NA = in_sizes[0] / 128;
    int NE = in_sizes[1] / 128;
    int NF = in_sizes[2] / 128;

    float *agg, *cnt, *B;
    cudaGetSymbolAddress((void**)&agg, g_agg);
    cudaGetSymbolAddress((void**)&cnt, g_cnt);
    cudaGetSymbolAddress((void**)&B, g_B);

    float* out = (float*)d_out;
    float* out_a = out;
    float* out_e = out + (size_t)NA * 128;
    float* out_f = out + (size_t)(NA + NE) * 128;

    // EDGE_TYPES: (a->e), (a->f), (e->a), (e->f), (f->e)
    const float* xs[5] = {xa, xa, xe, xe, xf};
    const float* xd[5] = {xe, xf, xa, xf, xe};
    int nd[5]          = {NE, NF, NA, NF, NE};
    float* od[5]       = {out_e, out_f, out_a, out_f, out_e};
    bool accf[5]       = {false, false, false, true, true};

    for (int t = 0; t < 5; t++) {
        const int* sit = (const int*)d_in[3 + 2 * t];
        const int* dit = (const int*)d_in[4 + 2 * t];
        int E = in_sizes[3 + 2 * t];
        const float* wl = (const float*)d_in[13 + 3 * t];
        const float* bs = (const float*)d_in[14 + 3 * t];
        const float* wr = (const float*)d_in[15 + 3 * t];

        cudaMemsetAsync(agg, 0, (size_t)nd[t] * 128 * sizeof(float), 0);
        cudaMemsetAsync(cnt, 0, (size_t)nd[t] * sizeof(float), 0);
        prep_B_kernel<<<128, 256>>>(wl, wr, B);

        long long thr = (long long)E * 32;
        int sblk = (int)((thr + 255) / 256);
        scatter_kernel<<<sblk, 256>>>(xs[t], sit, dit, E, agg, cnt);

        int gblk = (nd[t] + 127) / 128;
        if (accf[t])
            sage_gemm_kernel<true><<<gblk, 256>>>(xd[t], agg, cnt, B, bs, od[t], nd[t]);
        else
            sage_gemm_kernel<false><<<gblk, 256>>>(xd[t], agg, cnt, B, bs, od[t], nd[t]);
    }
}

// round 2
// speedup vs baseline: 1.9104x; 1.9104x over previous
#include <cuda_runtime.h>
#include <math.h>

#define D 128

// ---------------------------------------------------------------------------
// Scratch (device globals — no dynamic allocation allowed)
// Combined agg buffer for all 5 edge types: NE+NF+NA+NF+NE = 700k rows.
// ---------------------------------------------------------------------------
#define MAXROWS 716800
__device__ float    g_agg[(size_t)MAXROWS * D];     // segment sums
__device__ float    g_cnt[MAXROWS];                 // segment counts
__device__ unsigned g_B[5 * 2 * D * D];             // tf32 bits: [t][wl|wr][n][k]

// ---------------------------------------------------------------------------
// prep: convert all 5 wl / wr matrices to tf32 bits. Layout [t][side][n*128+k]
// (this is exactly the ".col" B operand layout for mma: n-major, k contiguous)
// ---------------------------------------------------------------------------
struct PrepParams { const float* wl[5]; const float* wr[5]; };

__global__ void prep_kernel(PrepParams p) {
    int i = blockIdx.x * blockDim.x + threadIdx.x;      // 0 .. 163839
    int t = i >> 15;                                     // /32768
    int r = i & 32767;
    int side = r >> 14;
    int idx = r & 16383;
    float v = (side ? p.wr[t] : p.wl[t])[idx];
    unsigned u;
    asm("cvt.rna.tf32.f32 %0, %1;" : "=r"(u) : "f"(v));
    g_B[i] = u;
}

// ---------------------------------------------------------------------------
// Mega-scatter: one warp per edge across ALL 5 types. Each lane gathers a
// float4 of the source row and does a single 128-bit global reduction.
// ---------------------------------------------------------------------------
struct ScatParams {
    const float* xs[5];
    const int*   si[5];
    const int*   di[5];
    size_t aggOff[5];     // in floats
    size_t cntOff[5];     // in rows
    long long wPrefix[6]; // cumulative warp (=edge) counts
};

__global__ void scatter_kernel(ScatParams p) {
    long long gt = (long long)blockIdx.x * blockDim.x + threadIdx.x;
    long long w = gt >> 5;
    int c = (int)(gt & 31);
    if (w >= p.wPrefix[5]) return;
    int t = 0;
    while (w >= p.wPrefix[t + 1]) t++;
    int e = (int)(w - p.wPrefix[t]);

    int s = p.si[t][e];
    int d = p.di[t][e];
    float4 v = ((const float4*)(p.xs[t] + (size_t)s * D))[c];
    float* dst = g_agg + p.aggOff[t] + (size_t)d * D + c * 4;
    asm volatile("red.global.add.v4.f32 [%0], {%1,%2,%3,%4};"
                 :: "l"(dst), "f"(v.x), "f"(v.y), "f"(v.z), "f"(v.w)
                 : "memory");
    if (c == 0) atomicAdd(g_cnt + p.cntOff[t] + d, 1.0f);
}

// ---------------------------------------------------------------------------
// Mega-GEMM (tf32 mma.sync.m16n8k8):
//   C[M x 128] = [x_dst | agg/max(cnt,1)] (M x 256) @ [wl^T ; wr^T]
// then + bias, row L2-normalize, and red.v2-accumulate into zeroed out.
// Block = 256 thr (8 warps, 4x2 over M x N), tile 128x128, BK=32, K=256.
// Warp tile 32x64 -> 2 m-tiles x 8 n-tiles of m16n8k8.
// ---------------------------------------------------------------------------
__device__ __forceinline__ void mma_tf32(float* c, const unsigned* a,
                                         unsigned b0, unsigned b1) {
    asm volatile(
        "mma.sync.aligned.m16n8k8.row.col.f32.tf32.tf32.f32 "
        "{%0,%1,%2,%3}, {%4,%5,%6,%7}, {%8,%9}, {%0,%1,%2,%3};"
        : "+f"(c[0]), "+f"(c[1]), "+f"(c[2]), "+f"(c[3])
        : "r"(a[0]), "r"(a[1]), "r"(a[2]), "r"(a[3]), "r"(b0), "r"(b1));
}

struct GemmParams {
    const float* xd[5];
    const float* bias[5];
    float*       out[5];
    size_t aggOff[5];
    size_t cntOff[5];
    int    nd[5];
    int    blkPrefix[6];
};

__global__ __launch_bounds__(256) void gemm_kernel(GemmParams p) {
    // block -> type
    int b = blockIdx.x;
    int t = 0;
    while (b >= p.blkPrefix[t + 1]) t++;
    int rowBase = (b - p.blkPrefix[t]) * 128;
    int n_dst = p.nd[t];
    const float* xd  = p.xd[t];
    const float* agg = g_agg + p.aggOff[t];
    const float* cnt = g_cnt + p.cntOff[t];
    const unsigned* Bl = g_B + (size_t)t * 32768;   // wl part [n][k]
    const unsigned* Br = Bl + 16384;                // wr part [n][k]

    __shared__ unsigned As[128][36];   // [row][k], stride 36 -> conflict-free
    __shared__ unsigned Bs[128][36];   // [n][k]
    __shared__ float invc_s[128];
    __shared__ float rowsum[2][128];

    int tid = threadIdx.x;
    int wid = tid >> 5, lane = tid & 31;
    int warpM = wid & 3, warpN = wid >> 2;
    int lq = lane & 3;        // quad lane
    int lr = lane >> 2;       // row-in-group

    if (tid < 128) {
        int gr = rowBase + tid;
        float cc = (gr < n_dst) ? cnt[gr] : 1.0f;
        invc_s[tid] = 1.0f / fmaxf(cc, 1.0f);
    }

    float acc[2][8][4];
#pragma unroll
    for (int mt = 0; mt < 2; mt++)
#pragma unroll
        for (int nt = 0; nt < 8; nt++)
#pragma unroll
            for (int r = 0; r < 4; r++) acc[mt][nt][r] = 0.f;

    for (int kt = 0; kt < 8; kt++) {
        bool isAgg = (kt >= 4);
        int kLocal = (kt & 3) * 32;
        const float* srcA = isAgg ? agg : xd;
        const unsigned* Bp = isAgg ? Br : Bl;

        if (kt) __syncthreads();

        // A tile: 128 rows x 32 k, tf32-convert, [row][k] stride 36
#pragma unroll
        for (int it = 0; it < 4; it++) {
            int f = it * 256 + tid;          // 0..1023 float4 items
            int r = f >> 3;
            int c4 = (f & 7) * 4;
            int gr = rowBase + r;
            float4 v = make_float4(0.f, 0.f, 0.f, 0.f);
            if (gr < n_dst)
                v = *(const float4*)(srcA + (size_t)gr * D + kLocal + c4);
            if (isAgg) {
                float s = invc_s[r];
                v.x *= s; v.y *= s; v.z *= s; v.w *= s;
            }
            unsigned u0, u1, u2, u3;
            asm("cvt.rna.tf32.f32 %0, %1;" : "=r"(u0) : "f"(v.x));
            asm("cvt.rna.tf32.f32 %0, %1;" : "=r"(u1) : "f"(v.y));
            asm("cvt.rna.tf32.f32 %0, %1;" : "=r"(u2) : "f"(v.z));
            asm("cvt.rna.tf32.f32 %0, %1;" : "=r"(u3) : "f"(v.w));
            As[r][c4 + 0] = u0; As[r][c4 + 1] = u1;
            As[r][c4 + 2] = u2; As[r][c4 + 3] = u3;
        }
        // B tile: 128 n x 32 k (already tf32 bits)
#pragma unroll
        for (int it = 0; it < 4; it++) {
            int f = it * 256 + tid;
            int r = f >> 3;
            int c4 = (f & 7) * 4;
            uint4 u = *(const uint4*)(Bp + (size_t)r * D + kLocal + c4);
            Bs[r][c4 + 0] = u.x; Bs[r][c4 + 1] = u.y;
            Bs[r][c4 + 2] = u.z; Bs[r][c4 + 3] = u.w;
        }
        __syncthreads();

#pragma unroll
        for (int k8 = 0; k8 < 4; k8++) {
            int kq = k8 * 8 + lq;
            unsigned a[2][4];
#pragma unroll
            for (int mt = 0; mt < 2; mt++) {
                int r0 = warpM * 32 + mt * 16 + lr;
                a[mt][0] = As[r0][kq];
                a[mt][1] = As[r0 + 8][kq];
                a[mt][2] = As[r0][kq + 4];
                a[mt][3] = As[r0 + 8][kq + 4];
            }
#pragma unroll
            for (int nt = 0; nt < 8; nt++) {
                int n0 = warpN * 64 + nt * 8 + lr;
                unsigned b0 = Bs[n0][kq];
                unsigned b1 = Bs[n0][kq + 4];
                mma_tf32(acc[0][nt], a[0], b0, b1);
                mma_tf32(acc[1][nt], a[1], b0, b1);
            }
        }
    }

    // ---- epilogue: bias, row L2-norm, red.v2 store ----
    const float* bias = p.bias[t];
    float biasv[16];
#pragma unroll
    for (int nt = 0; nt < 8; nt++) {
        float2 bb = *(const float2*)(bias + warpN * 64 + nt * 8 + 2 * lq);
        biasv[2 * nt] = bb.x;
        biasv[2 * nt + 1] = bb.y;
    }

    float ps[2][2] = {{0.f, 0.f}, {0.f, 0.f}};
#pragma unroll
    for (int mt = 0; mt < 2; mt++)
#pragma unroll
        for (int nt = 0; nt < 8; nt++) {
            acc[mt][nt][0] += biasv[2 * nt];
            acc[mt][nt][1] += biasv[2 * nt + 1];
            acc[mt][nt][2] += biasv[2 * nt];
            acc[mt][nt][3] += biasv[2 * nt + 1];
            ps[mt][0] += acc[mt][nt][0] * acc[mt][nt][0]
                       + acc[mt][nt][1] * acc[mt][nt][1];
            ps[mt][1] += acc[mt][nt][2] * acc[mt][nt][2]
                       + acc[mt][nt][3] * acc[mt][nt][3];
        }
#pragma unroll
    for (int mt = 0; mt < 2; mt++)
#pragma unroll
        for (int h = 0; h < 2; h++) {
            float v = ps[mt][h];
            v += __shfl_xor_sync(0xffffffffu, v, 1);
            v += __shfl_xor_sync(0xffffffffu, v, 2);
            ps[mt][h] = v;   // full 64-col partial, all 4 quad lanes
            if (lq == 0)
                rowsum[warpN][warpM * 32 + mt * 16 + h * 8 + lr] = v;
        }
    __syncthreads();

    float* outp = p.out[t];
#pragma unroll
    for (int mt = 0; mt < 2; mt++)
#pragma unroll
        for (int h = 0; h < 2; h++) {
            int rloc = warpM * 32 + mt * 16 + h * 8 + lr;
            int gr = rowBase + rloc;
            if (gr >= n_dst) continue;
            float ss = rowsum[0][rloc] + rowsum[1][rloc];
            float inv = 1.f / fmaxf(sqrtf(ss), 1e-12f);
#pragma unroll
            for (int nt = 0; nt < 8; nt++) {
                float vx = acc[mt][nt][h * 2 + 0] * inv;
                float vy = acc[mt][nt][h * 2 + 1] * inv;
                float* pp = outp + (size_t)gr * D + warpN * 64 + nt * 8 + 2 * lq;
                asm volatile("red.global.add.v2.f32 [%0], {%1,%2};"
                             :: "l"(pp), "f"(vx), "f"(vy) : "memory");
            }
        }
}

// ---------------------------------------------------------------------------
// Host orchestration — 6 graph nodes: 3 memsets, prep, scatter, gemm.
// ---------------------------------------------------------------------------
extern "C" void kernel_launch(void* const* d_in, const int* in_sizes, int n_in,
                              void* d_out, int out_size) {
    const float* xa = (const float*)d_in[0];
    const float* xe = (const float*)d_in[1];
    const float* xf = (const float*)d_in[2];
    int NA = in_sizes[0] / D;
    int NE = in_sizes[1] / D;
    int NF = in_sizes[2] / D;

    float* aggPtr; float* cntPtr;
    cudaGetSymbolAddress((void**)&aggPtr, g_agg);
    cudaGetSymbolAddress((void**)&cntPtr, g_cnt);

    float* out = (float*)d_out;
    float* out_a = out;
    float* out_e = out + (size_t)NA * D;
    float* out_f = out + (size_t)(NA + NE) * D;

    // EDGE_TYPES: (a->e), (a->f), (e->a), (e->f), (f->e)
    const float* xs[5] = {xa, xa, xe, xe, xf};
    const float* xd[5] = {xe, xf, xa, xf, xe};
    int nd[5]          = {NE, NF, NA, NF, NE};
    float* od[5]       = {out_e, out_f, out_a, out_f, out_e};

    PrepParams pp;
    ScatParams sp;
    GemmParams gp;

    size_t rowCum = 0;
    long long wCum = 0;
    int blkCum = 0;
    sp.wPrefix[0] = 0;
    gp.blkPrefix[0] = 0;
    for (int t = 0; t < 5; t++) {
        pp.wl[t] = (const float*)d_in[13 + 3 * t];
        pp.wr[t] = (const float*)d_in[15 + 3 * t];
        sp.xs[t] = xs[t];
        sp.si[t] = (const int*)d_in[3 + 2 * t];
        sp.di[t] = (const int*)d_in[4 + 2 * t];
        sp.aggOff[t] = rowCum * D;
        sp.cntOff[t] = rowCum;
        gp.xd[t] = xd[t];
        gp.bias[t] = (const float*)d_in[14 + 3 * t];
        gp.out[t] = od[t];
        gp.aggOff[t] = rowCum * D;
        gp.cntOff[t] = rowCum;
        gp.nd[t] = nd[t];
        rowCum += (size_t)nd[t];
        wCum += in_sizes[3 + 2 * t];
        blkCum += (nd[t] + 127) / 128;
        sp.wPrefix[t + 1] = wCum;
        gp.blkPrefix[t + 1] = blkCum;
    }

    // zero accumulators and output
    cudaMemsetAsync(aggPtr, 0, rowCum * D * sizeof(float), 0);
    cudaMemsetAsync(cntPtr, 0, rowCum * sizeof(float), 0);
    cudaMemsetAsync(d_out, 0, (size_t)out_size * sizeof(float), 0);

    prep_kernel<<<(5 * 2 * D * D) / 256, 256>>>(pp);

    long long thr = wCum * 32;
    int sblk = (int)((thr + 255) / 256);
    scatter_kernel<<<sblk, 256>>>(sp);

    gemm_kernel<<<blkCum, 256>>>(gp);
}